// round 15
// baseline (speedup 1.0000x reference)
#include <cuda_runtime.h>
#include <math.h>
#include <cstdint>

// Fixed shape: query_len = key_len = 2048, 8 fp32 channels, TRUNC = 200.
#define QL 2048
#define KL 2048
#define NT 201              // distinct T values 0..200 (T>200 -> T=0 vector)
#define THREADS 256
#define CPIX 1024           // const staging buffer: 1024 px = 32 KB per copy
#define BAND_MAX 416        // band <= 401 px

__device__ __forceinline__ uint32_t smem_u32(const void* p) {
    uint32_t a;
    asm("{ .reg .u64 t; cvta.to.shared.u64 t, %1; cvt.u32.u64 %0, t; }"
        : "=r"(a) : "l"(p));
    return a;
}

__device__ __forceinline__ void bulk_s2g(float4* g, uint32_t s, int bytes) {
    asm volatile("cp.async.bulk.global.shared::cta.bulk_group [%0], [%1], %2;"
                 :: "l"(g), "r"(s), "r"(bytes) : "memory");
}

// One CTA = one full row. Bigger bulk copies (up to 32 KB; ~7000 total vs
// ~9800 in R14) amortize per-copy TMA dispatch, and prologue count halves.
// Warp-specialized prologue kept from R14: warp 0 fills the const buffer and
// posts the const copies after only a __syncwarp; warps 1-7 build the LUT
// concurrently. Exit waits for SMEM-read completion only.
__global__ __launch_bounds__(THREADS) void fill_row5_kernel(
    const float* __restrict__ eta, const float* __restrict__ nu,
    const float* __restrict__ theta, float4* __restrict__ out)
{
    __shared__ __align__(16) float4 cbuf[CPIX * 2];      // 32 KB, constant
    __shared__ __align__(16) float4 bbuf[BAND_MAX * 2];  // 13 KB, band
    __shared__ __align__(16) float4 lut[2 * NT];         // 6.4 KB

    const int tid = threadIdx.x;
    const int i   = blockIdx.x;                  // row

    const float4 farA = make_float4(1.f, 1.f, 0.f, 0.f);
    const float4 farB = make_float4(1.f, 1.f, 1.f, 0.f);
    float4* gp = out + (size_t)i * (2 * KL);

    // Band |i-j| <= 200 clamped to [0, KL).
    const int lo = (i - 200 > 0) ? i - 200 : 0;
    const int hi = (i + 200 < KL - 1) ? i + 200 : KL - 1;

    if (tid < 32) {
        // ---- warp 0: const buffer fill + post const copies ASAP ----
#pragma unroll
        for (int k = 0; k < (CPIX * 2) / 32; k++) {
            int f = k * 32 + tid;
            cbuf[f] = (f & 1) ? farB : farA;
        }
        __syncwarp();
        if (tid == 0) {
            asm volatile("fence.proxy.async.shared::cta;" ::: "memory");
            const uint32_t cb = smem_u32(cbuf);
            int rem = lo, off = 0;                   // left const [0, lo)
            while (rem > 0) {
                int n = (rem < CPIX) ? rem : CPIX;
                bulk_s2g(gp + 2 * off, cb, n * 32);
                off += n; rem -= n;
            }
            rem = (KL - 1) - hi; off = hi + 1;       // right const (hi, KL)
            while (rem > 0) {
                int n = (rem < CPIX) ? rem : CPIX;
                bulk_s2g(gp + 2 * off, cb, n * 32);
                off += n; rem -= n;
            }
            asm volatile("cp.async.bulk.commit_group;" ::: "memory");
        }
    } else if (tid - 32 < NT) {
        // ---- warps 1-7: LUT build, concurrent with warp 0 ----
        // (fp32 + __powf; rel_err ~3.4e-9 measured in R14)
        const int t = tid - 32;
        float lambda = tanhf(eta[0]);
        float gamma  = 1.0f / (1.0f + expf(-nu[0]));
        float th     = theta[0];
        float T      = (float)t;

        float gT = __powf(gamma, T);
        float s, c;  sincosf(T * th, &s, &c);
        float v0 = gT * c;            // ch0, ch1
        float v2 = gT * s;            // ch2, ch3

        float L2d = (t % 2  == 0) ? T * 0.5f    : 0.0f;
        float L4d = (t % 4  == 0) ? T * 0.25f   : 0.0f;
        float L8d = (t % 8  == 0) ? T * 0.125f  : 0.0f;
        float L16 = (t % 16 == 0) ? T * 0.0625f : 0.0f;

        float v4 = __powf(lambda, L2d);                 // ch4
        float v5 = __powf(lambda, L4d);                 // ch5
        float s8, c8;   sincosf(L8d * th, &s8, &c8);
        float s16, c16; sincosf(L16 * th, &s16, &c16);
        float v6 = __powf(gamma, L8d) * c8;             // ch6
        float v7 = __powf(gamma, L16) * s16;            // ch7

        lut[2 * t]     = make_float4(v0, v0, v2, v2);
        lut[2 * t + 1] = make_float4(v4, v5, v6, v7);
    }

    __syncthreads();    // lut visible to all warps

    // ---- band fill (<= 401 px; T <= 200 by construction) ----
    const int npix = hi - lo + 1;
    for (int k = tid; k < npix; k += THREADS) {
        int j = lo + k;
        int T = i - j;  T = (T < 0) ? -T : T;
        bbuf[2 * k]     = lut[2 * T];
        bbuf[2 * k + 1] = lut[2 * T + 1];
    }
    __syncthreads();

    // ---- band copy; exit after SMEM-read completion only ----
    if (tid == 0) {
        asm volatile("fence.proxy.async.shared::cta;" ::: "memory");
        bulk_s2g(gp + 2 * lo, smem_u32(bbuf), npix * 32);
        asm volatile("cp.async.bulk.commit_group;" ::: "memory");
        asm volatile("cp.async.bulk.wait_group.read 0;" ::: "memory");
    }
}

extern "C" void kernel_launch(void* const* d_in, const int* in_sizes, int n_in,
                              void* d_out, int out_size) {
    const float* eta   = (const float*)d_in[0];
    const float* nu    = (const float*)d_in[1];
    const float* theta = (const float*)d_in[2];

    fill_row5_kernel<<<QL, THREADS>>>(eta, nu, theta, (float4*)d_out);
}

// round 16
// speedup vs baseline: 1.0605x; 1.0605x over previous
#include <cuda_runtime.h>
#include <math.h>
#include <cstdint>

// Fixed shape: query_len = key_len = 2048, 8 fp32 channels, TRUNC = 200.
#define QL 2048
#define KL 2048
#define NT 201              // distinct T values 0..200 (T>200 -> T=0 vector)
#define THREADS 256
#define HALF 1024           // CTA = half-row (1024 px = 32 KB out)
#define CPIX 512            // const staging buffer: 512 px = 16 KB
#define BAND_MAX 416        // band within a half-row <= 401 px

__device__ __forceinline__ uint32_t smem_u32(const void* p) {
    uint32_t a;
    asm("{ .reg .u64 t; cvta.to.shared.u64 t, %1; cvt.u32.u64 %0, t; }"
        : "=r"(a) : "l"(p));
    return a;
}

__device__ __forceinline__ void bulk_s2g(float4* g, uint32_t s, int bytes) {
    asm volatile("cp.async.bulk.global.shared::cta.bulk_group [%0], [%1], %2;"
                 :: "l"(g), "r"(s), "r"(bytes) : "memory");
}

// R14 (best: half-row CTAs, warp-specialized prologue, read-only drain)
// + direct band scatter: the band is the LUT mirrored around j == i, so
// warps 1-7 write each computed entry straight into its <=2 band-buffer
// slots. Deletes the lut[] array, the separate band fill loop, and one
// __syncthreads from the band-CTA critical path.
__global__ __launch_bounds__(THREADS) void fill_half5_kernel(
    const float* __restrict__ eta, const float* __restrict__ nu,
    const float* __restrict__ theta, float4* __restrict__ out)
{
    __shared__ __align__(16) float4 cbuf[CPIX * 2];      // 16 KB, constant
    __shared__ __align__(16) float4 bbuf[BAND_MAX * 2];  // 13 KB, band

    const int tid   = threadIdx.x;
    const int i     = blockIdx.x >> 1;              // row
    const int pbase = (blockIdx.x & 1) * HALF;      // half offset in row

    const float4 farA = make_float4(1.f, 1.f, 0.f, 0.f);
    const float4 farB = make_float4(1.f, 1.f, 1.f, 0.f);
    float4* gp = out + ((size_t)i * KL + pbase) * 2;

    // Band |i-j| <= 200 clamped to this half-row [pbase, pbase+HALF).
    int lo = i - 200;  if (lo < pbase) lo = pbase;
    int hi = i + 200;  if (hi > pbase + HALF - 1) hi = pbase + HALF - 1;
    const bool has_band = (lo <= hi);               // block-uniform

    if (tid < 32) {
        // ---- warp 0: const buffer fill + post const copies ASAP ----
#pragma unroll
        for (int k = 0; k < (CPIX * 2) / 32; k++) {
            int f = k * 32 + tid;
            cbuf[f] = (f & 1) ? farB : farA;
        }
        __syncwarp();
        if (tid == 0) {
            asm volatile("fence.proxy.async.shared::cta;" ::: "memory");
            const uint32_t cb = smem_u32(cbuf);
            if (!has_band) {
                bulk_s2g(gp,            cb, CPIX * 32);
                bulk_s2g(gp + 2 * CPIX, cb, CPIX * 32);
            } else {
                int rem = lo - pbase, off = 0;        // left const segment
                while (rem > 0) {
                    int n = (rem < CPIX) ? rem : CPIX;
                    bulk_s2g(gp + 2 * off, cb, n * 32);
                    off += n; rem -= n;
                }
                rem = (pbase + HALF - 1) - hi;        // right const segment
                off = hi + 1 - pbase;
                while (rem > 0) {
                    int n = (rem < CPIX) ? rem : CPIX;
                    bulk_s2g(gp + 2 * off, cb, n * 32);
                    off += n; rem -= n;
                }
            }
            asm volatile("cp.async.bulk.commit_group;" ::: "memory");
        }
    } else if (has_band && tid - 32 < NT) {
        // ---- warps 1-7: compute entry t, scatter to j = i-t and i+t ----
        // (fp32 + __powf; rel_err ~3.4e-9 measured R14/R15)
        const int t = tid - 32;
        float lambda = tanhf(eta[0]);
        float gamma  = 1.0f / (1.0f + expf(-nu[0]));
        float th     = theta[0];
        float T      = (float)t;

        float gT = __powf(gamma, T);
        float s, c;  sincosf(T * th, &s, &c);
        float v0 = gT * c;            // ch0, ch1
        float v2 = gT * s;            // ch2, ch3

        float L2d = (t % 2  == 0) ? T * 0.5f    : 0.0f;
        float L4d = (t % 4  == 0) ? T * 0.25f   : 0.0f;
        float L8d = (t % 8  == 0) ? T * 0.125f  : 0.0f;
        float L16 = (t % 16 == 0) ? T * 0.0625f : 0.0f;

        float v4 = __powf(lambda, L2d);                 // ch4
        float v5 = __powf(lambda, L4d);                 // ch5
        float s8, c8;   sincosf(L8d * th, &s8, &c8);
        float s16, c16; sincosf(L16 * th, &s16, &c16);
        float v6 = __powf(gamma, L8d) * c8;             // ch6
        float v7 = __powf(gamma, L16) * s16;            // ch7

        const float4 a = make_float4(v0, v0, v2, v2);
        const float4 b = make_float4(v4, v5, v6, v7);

        int j = i - t;                                  // left mirror
        if (j >= lo && j <= hi) {
            int k = j - lo;
            bbuf[2 * k]     = a;
            bbuf[2 * k + 1] = b;
        }
        j = i + t;                                      // right mirror
        if (t > 0 && j >= lo && j <= hi) {
            int k = j - lo;
            bbuf[2 * k]     = a;
            bbuf[2 * k + 1] = b;
        }
    }

    if (has_band) {
        __syncthreads();    // band buffer complete

        // ---- band copy ----
        if (tid == 0) {
            asm volatile("fence.proxy.async.shared::cta;" ::: "memory");
            const int npix = hi - lo + 1;
            bulk_s2g(gp + 2 * (lo - pbase), smem_u32(bbuf), npix * 32);
            asm volatile("cp.async.bulk.commit_group;" ::: "memory");
        }
    }

    // Exit after SMEM-read completion only; global visibility is covered
    // by kernel-completion semantics.
    if (tid == 0)
        asm volatile("cp.async.bulk.wait_group.read 0;" ::: "memory");
}

extern "C" void kernel_launch(void* const* d_in, const int* in_sizes, int n_in,
                              void* d_out, int out_size) {
    const float* eta   = (const float*)d_in[0];
    const float* nu    = (const float*)d_in[1];
    const float* theta = (const float*)d_in[2];

    fill_half5_kernel<<<QL * 2, THREADS>>>(eta, nu, theta, (float4*)d_out);
}